// round 12
// baseline (speedup 1.0000x reference)
#include <cuda_runtime.h>

// ---------------------------------------------------------------------------
// MeanPooling: out[b,:] = mean of x[i,:] over rows i with batch[i]==b
// x: (N,128) fp32, batch: (N,) sorted int64-or-int32, out: (4096,128) fp32
// R9: counts-BEFORE-accum, done cheaply. k_pre: zero out + linear boundary
// detection on sorted batch -> g_lo/g_hi per nonempty segment (non-atomic,
// idempotent writes; stale entries only for empty segments, never read).
// k_accum: segmented warp reduction; each flush scales by
// 1/(g_hi[seg]-g_lo[seg]) and atomicAdds directly into d_out. No epilogue
// kernel, no scratch sums, no resets needed -> deterministic every replay.
// ---------------------------------------------------------------------------

#define D 128
#define MAXB 8192

__device__ int g_lo[MAXB];   // first row index of segment (nonempty segs only)
__device__ int g_hi[MAXB];   // one-past-last row index (nonempty segs only)

// Detect dtype of batch buffer. Reads only within the first n 32-bit words
// (in-bounds for both layouts). int64 LE: odd words are high halves == 0
// (values < 4096). int32 sorted data: tail words ~ num_graphs-1 (nonzero).
__device__ __forceinline__ int detect_is64(const unsigned int* __restrict__ w,
                                           int n) {
    int top = n - 1;
    if ((top & 1) == 0) top--;          // largest odd index <= n-1
    int nz = 0;
#pragma unroll 1
    for (int k = 0; k < 32; k++) {
        int idx = top - 2 * k;
        if (idx < 1) break;
        if (w[idx] != 0u) { nz = 1; break; }
    }
    return (nz == 0) ? 1 : 0;
}

// k_pre: zero output + write segment boundaries (linear, streaming-parallel).
__global__ void __launch_bounds__(256) k_pre(const void* __restrict__ batch,
                                             float4* __restrict__ out4,
                                             int n, int n4) {
    const int tid = blockIdx.x * blockDim.x + threadIdx.x;
    const int nt = gridDim.x * blockDim.x;

    // zero the output (atomic accumulation target)
    for (int i = tid; i < n4; i += nt)
        out4[i] = make_float4(0.f, 0.f, 0.f, 0.f);

    const int is64 = detect_is64((const unsigned int*)batch, n);
    const int* bw = (const int*)batch;
    const int ish = is64 ? 1 : 0;       // int64 LE: low word at bw[2i]

    if (tid == 0) {
        g_lo[bw[0]] = 0;
        g_hi[bw[(n - 1) << ish]] = n;
    }
    // boundaries: exactly-one-writer, idempotent
    for (int i = tid + 1; i < n; i += nt) {
        int a = bw[(i - 1) << ish];
        int b = bw[i << ish];
        if (a != b) {
            g_hi[a] = i;
            g_lo[b] = i;
        }
    }
}

__device__ __forceinline__ void flush_seg(float* __restrict__ out, int seg,
                                          int lane, const float4& acc) {
    int lo = g_lo[seg];                 // L2-hot (written by k_pre)
    int hi = g_hi[seg];
    float rinv = __frcp_rn((float)(hi - lo));   // count >= 1 for flushed segs
    float* p = out + (size_t)seg * D + lane * 4;
    atomicAdd(p + 0, acc.x * rinv);
    atomicAdd(p + 1, acc.y * rinv);
    atomicAdd(p + 2, acc.z * rinv);
    atomicAdd(p + 3, acc.w * rinv);
}

__global__ void __launch_bounds__(256, 6) k_accum(const float4* __restrict__ x4,
                                                  const void* __restrict__ batch,
                                                  float* __restrict__ out,
                                                  int n) {
    const int lane = threadIdx.x & 31;
    const int wid = (blockIdx.x << 3) + (threadIdx.x >> 5);
    const int tw = gridDim.x << 3;
    const int per = (n + tw - 1) / tw;
    int r0 = wid * per;
    int r1 = min(r0 + per, n);
    if (r0 >= r1) return;

    const int is64 = detect_is64((const unsigned int*)batch, n);
    const int* bw = (const int*)batch;
    const int ish = is64 ? 1 : 0;       // int64 LE: low word at bw[2i]

    float4 acc = make_float4(0.f, 0.f, 0.f, 0.f);
    int cur = bw[r0 << ish];

    int r = r0;
    // 4 rows per iteration; all 4 float4 loads issued before the boundary
    // branch (streaming hint: x has no reuse).
    for (; r + 4 <= r1; r += 4) {
        const float4* p = x4 + (size_t)r * 32 + lane;
        float4 v0 = __ldcs(p);
        float4 v1 = __ldcs(p + 32);
        float4 v2 = __ldcs(p + 64);
        float4 v3 = __ldcs(p + 96);
        int blast = bw[(r + 3) << ish];
        if (blast == cur) {
            acc.x += v0.x + v1.x + v2.x + v3.x;
            acc.y += v0.y + v1.y + v2.y + v3.y;
            acc.z += v0.z + v1.z + v2.z + v3.z;
            acc.w += v0.w + v1.w + v2.w + v3.w;
        } else {
            float4 v[4] = {v0, v1, v2, v3};
#pragma unroll
            for (int k = 0; k < 4; k++) {
                int b = bw[(r + k) << ish];
                if (b != cur) {
                    flush_seg(out, cur, lane, acc);
                    acc = make_float4(0.f, 0.f, 0.f, 0.f);
                    cur = b;
                }
                acc.x += v[k].x; acc.y += v[k].y;
                acc.z += v[k].z; acc.w += v[k].w;
            }
        }
    }
    // Tail rows
    for (; r < r1; r++) {
        int b = bw[r << ish];
        if (b != cur) {
            flush_seg(out, cur, lane, acc);
            acc = make_float4(0.f, 0.f, 0.f, 0.f);
            cur = b;
        }
        float4 v = __ldcs(x4 + (size_t)r * 32 + lane);
        acc.x += v.x; acc.y += v.y; acc.z += v.z; acc.w += v.w;
    }
    flush_seg(out, cur, lane, acc);
}

extern "C" void kernel_launch(void* const* d_in, const int* in_sizes, int n_in,
                              void* d_out, int out_size) {
    const float* x = (const float*)d_in[0];
    const void* batch = d_in[1];

    int n = in_sizes[0] / D;               // number of rows
    int n4 = out_size / 4;                 // float4 elements in output
    float* out = (float*)d_out;

    k_pre<<<592, 256>>>(batch, (float4*)out, n, n4);
    k_accum<<<888, 256>>>((const float4*)x, batch, out, n);
}